// round 11
// baseline (speedup 1.0000x reference)
#include <cuda_runtime.h>
#include <cuda_bf16.h>
#include <math.h>

#define CDIV(a,b) (((a)+(b)-1)/(b))

// Dimensions: B=512, SC=48, ST=16, E=512, H=256, N_CHARS=128, N_TAGS=64
constexpr size_t SZ(size_t n) { return (n + 255) & ~(size_t)255; }

constexpr size_t O_CS    = 0;                                    // [512,48,192]
constexpr size_t O_TS    = O_CS    + SZ(24576ull*192);           // [512,16,128]
constexpr size_t O_DECIN = O_TS    + SZ(8192ull*128);            // [512,48,128]
constexpr size_t O_XCF   = O_DECIN + SZ(24576ull*128);           // [512,48,1024]
constexpr size_t O_XCB   = O_XCF   + SZ(24576ull*1024);
constexpr size_t O_XTF   = O_XCB   + SZ(24576ull*1024);          // [512,16,1024]
constexpr size_t O_XTB   = O_XTF   + SZ(8192ull*1024);
constexpr size_t O_XDEC  = O_XTB   + SZ(8192ull*1024);           // [512,48,2048]
constexpr size_t O_CO    = O_XDEC  + SZ(24576ull*2048);          // [512,48,512]
constexpr size_t O_TO    = O_CO    + SZ(24576ull*512);           // [512,16,512]
constexpr size_t O_HS    = O_TO    + SZ(8192ull*512);            // [512,48,512]
constexpr size_t O_CCF   = O_HS    + SZ(24576ull*512);           // 2x[512,256]
constexpr size_t O_CCB   = O_CCF   + SZ(2ull*512*256);
constexpr size_t O_CTF   = O_CCB   + SZ(2ull*512*256);
constexpr size_t O_CTB   = O_CTF   + SZ(2ull*512*256);
constexpr size_t O_DC    = O_CTB   + SZ(2ull*512*256);           // 2x[512,512]
constexpr size_t O_H0    = O_DC    + SZ(2ull*512*512);
constexpr size_t O_C0    = O_H0    + SZ(512ull*512);
constexpr size_t O_QC    = O_C0    + SZ(512ull*512);             // [512,48,512]
constexpr size_t O_QT    = O_QC    + SZ(24576ull*512);
constexpr size_t O_KVC   = O_QT    + SZ(24576ull*512);           // [512,48,1024]
constexpr size_t O_KVT   = O_KVC   + SZ(24576ull*1024);          // [512,16,1024]
constexpr size_t O_OC    = O_KVT   + SZ(8192ull*1024);           // [512,48,512]
constexpr size_t O_OT    = O_OC    + SZ(24576ull*512);
constexpr size_t O_CAT   = O_OT    + SZ(24576ull*512);           // [24576,1024]
constexpr size_t O_LOG   = O_CAT   + SZ(24576ull*1024);          // [24576,128]
constexpr size_t O_END   = O_LOG   + SZ(24576ull*128);

__device__ float g_scratch[O_END];

// ---------------------------------------------------------------------------
// grid-wide barrier for persistent kernels (always 128 blocks)
// ---------------------------------------------------------------------------
__device__ unsigned g_cnt = 0;
__device__ unsigned g_gen = 0;

__device__ __forceinline__ void grid_barrier128() {
    __syncthreads();
    __threadfence();
    if (threadIdx.x == 0) {
        volatile unsigned* vg = &g_gen;
        unsigned my = *vg;
        if (atomicInc(&g_cnt, 127u) == 127u) {
            atomicAdd(&g_gen, 1u);
        } else {
            while (*vg == my) __nanosleep(64);
        }
    }
    __syncthreads();
}

// ---------------------------------------------------------------------------
__global__ void prep_kernel(const int* __restrict__ li,
                            const float* __restrict__ char_seq,
                            const float* __restrict__ tagset,
                            const float* __restrict__ lang_embeds,
                            float* __restrict__ cs, float* __restrict__ ts) {
    int idx = blockIdx.x * blockDim.x + threadIdx.x;
    const int n1 = 512 * 48 * 192;
    const int n2 = 512 * 16 * 128;
    if (idx < n1) {
        int b = idx / (48 * 192);
        int rem = idx - b * 48 * 192;
        int s = rem / 192, k = rem - s * 192;
        float v;
        if (k < 128) v = char_seq[(b * 48 + s) * 128 + k];
        else         v = lang_embeds[li[li[b]] * 64 + (k - 128)];
        cs[idx] = v;
    } else if (idx < n1 + n2) {
        int j = idx - n1;
        int b = j / (16 * 128);
        int rem = j - b * 16 * 128;
        int s = rem / 128, k = rem - s * 128;
        float v;
        if (k < 64) v = tagset[(b * 16 + s) * 64 + k];
        else        v = lang_embeds[li[li[b]] * 64 + (k - 64)];
        ts[j] = v;
    }
}

__global__ void build_decin(const float* __restrict__ labels, float* __restrict__ decin) {
    int idx = blockIdx.x * blockDim.x + threadIdx.x;
    if (idx >= 512 * 48 * 128) return;
    int t = (idx >> 7) % 48;
    decin[idx] = (t == 0) ? 0.f : labels[idx];
}

// ---------------------------------------------------------------------------
// tf32 helpers: 3-term compensated (Ah*Bh + Ah*Bl + Al*Bh ~ fp32 accuracy)
// ---------------------------------------------------------------------------
__device__ __forceinline__ unsigned f2tf(float x) {
    unsigned r; asm("cvt.rna.tf32.f32 %0, %1;" : "=r"(r) : "f"(x)); return r;
}
__device__ __forceinline__ void split_tf(float x, unsigned& h, unsigned& l) {
    h = f2tf(x);
    l = f2tf(x - __uint_as_float(h));
}
__device__ __forceinline__ void mma8(float* c, const unsigned* a, const unsigned* b) {
    asm volatile(
        "mma.sync.aligned.m16n8k8.row.col.f32.tf32.tf32.f32 "
        "{%0,%1,%2,%3}, {%4,%5,%6,%7}, {%8,%9}, {%0,%1,%2,%3};\n"
        : "+f"(c[0]), "+f"(c[1]), "+f"(c[2]), "+f"(c[3])
        : "r"(a[0]), "r"(a[1]), "r"(a[2]), "r"(a[3]), "r"(b[0]), "r"(b[1]));
}

// store one fp32 value as pre-split tf32 hi/lo into two smem regions
__device__ __forceinline__ void sts_split(float v, float* hi, float* lo, int pos) {
    unsigned h, l;
    split_tf(v, h, l);
    hi[pos] = __uint_as_float(h);
    lo[pos] = __uint_as_float(l);
}

// ---------------------------------------------------------------------------
// GEMM: C[m,n] = sum_k A[m,k]*W[n,k] + bias[n]. 128x128 tile, k-step 32,
// double-buffered, 512 threads = 16 warps (4m x 4n), warp tile 32x32.
// smem per stage: A_hi | A_lo | B_hi | B_lo, each 128 rows x 40 (k-permuted:
// within each k8 group element k sits at (k&3)*2 + (k>>2)) -> fragment pairs
// are single LDS.64, conflict-free. Pre-split: compute phase does NO cvt.
// Stage = 20480 floats; double buffer = 163840 bytes dynamic smem.
// ---------------------------------------------------------------------------
__device__ __forceinline__ void g_ldg(const float* __restrict__ A,
                                      const float* __restrict__ W,
                                      int K, int bm, int bn, int k0, int tid,
                                      float4* av, float4* wv) {
#pragma unroll
    for (int i = 0; i < 2; i++) {
        int idx = tid + i * 512;
        int row = idx >> 3, fc = idx & 7;
        av[i] = *(const float4*)(A + (size_t)(bm + row) * K + k0 + fc * 4);
        wv[i] = *(const float4*)(W + (size_t)(bn + row) * K + k0 + fc * 4);
    }
}

__device__ __forceinline__ void g_sts(float* __restrict__ buf, int tid,
                                      const float4* av, const float4* wv) {
    float* Ah = buf;
    float* Al = buf + 5120;
    float* Bh = buf + 10240;
    float* Bl = buf + 15360;
#pragma unroll
    for (int i = 0; i < 2; i++) {
        int idx = tid + i * 512;
        int row = idx >> 3, fc = idx & 7;
        int g = fc >> 1, up = fc & 1;
        int pos = row * 40 + g * 8 + up;
        sts_split(av[i].x, Ah, Al, pos);
        sts_split(av[i].y, Ah, Al, pos + 2);
        sts_split(av[i].z, Ah, Al, pos + 4);
        sts_split(av[i].w, Ah, Al, pos + 6);
        sts_split(wv[i].x, Bh, Bl, pos);
        sts_split(wv[i].y, Bh, Bl, pos + 2);
        sts_split(wv[i].z, Bh, Bl, pos + 4);
        sts_split(wv[i].w, Bh, Bl, pos + 6);
    }
}

__device__ __forceinline__ void ld_frag4(const float* base, unsigned* f) {
    float2 p = *(const float2*)base;
    float2 q = *(const float2*)(base + 320);   // +8 rows * 40
    f[0] = __float_as_uint(p.x);
    f[1] = __float_as_uint(q.x);
    f[2] = __float_as_uint(p.y);
    f[3] = __float_as_uint(q.y);
}
__device__ __forceinline__ void ld_frag2(const float* base, unsigned* f) {
    float2 p = *(const float2*)base;
    f[0] = __float_as_uint(p.x);
    f[1] = __float_as_uint(p.y);
}

__device__ __forceinline__ void g_compute(const float* __restrict__ buf,
                                          int wm, int wn, int gid, int tig,
                                          float (&acc)[2][4][4]) {
    const float* Ah = buf;
    const float* Al = buf + 5120;
    const float* Bh = buf + 10240;
    const float* Bl = buf + 15360;
#pragma unroll
    for (int ks = 0; ks < 4; ks++) {
        unsigned ah[2][4], al[2][4];
#pragma unroll
        for (int mt = 0; mt < 2; mt++) {
            int o = (wm * 32 + mt * 16 + gid) * 40 + ks * 8 + tig * 2;
            ld_frag4(Ah + o, ah[mt]);
            ld_frag4(Al + o, al[mt]);
        }
        unsigned bh[4][2], bl[4][2];
#pragma unroll
        for (int j = 0; j < 4; j++) {
            int o = (wn * 32 + j * 8 + gid) * 40 + ks * 8 + tig * 2;
            ld_frag2(Bh + o, bh[j]);
            ld_frag2(Bl + o, bl[j]);
        }
#pragma unroll
        for (int mt = 0; mt < 2; mt++)
#pragma unroll
            for (int j = 0; j < 4; j++) {
                float* c = acc[mt][j];
                mma8(c, ah[mt], bh[j]);
                mma8(c, ah[mt], bl[j]);
                mma8(c, al[mt], bh[j]);
            }
    }
}

__global__ __launch_bounds__(512) void gemm_mma(
    const float* __restrict__ A, const float* __restrict__ W,
    const float* __restrict__ bias, float* __restrict__ C,
    int M, int N, int K, int ldc)
{
    extern __shared__ float sbuf[];
    float* buf0 = sbuf;
    float* buf1 = sbuf + 20480;
    const int bm = blockIdx.y * 128;
    const int bn = blockIdx.x * 128;
    const int tid = threadIdx.x;
    const int wid = tid >> 5, lane = tid & 31;
    const int wm = wid >> 2, wn = wid & 3;
    const int gid = lane >> 2, tig = lane & 3;

    float acc[2][4][4];
#pragma unroll
    for (int i = 0; i < 2; i++)
#pragma unroll
        for (int j = 0; j < 4; j++)
#pragma unroll
            for (int r = 0; r < 4; r++) acc[i][j][r] = 0.f;

    const int NT = K >> 5;
    float4 av[2], wv[2];

    g_ldg(A, W, K, bm, bn, 0, tid, av, wv);
    g_sts(buf0, tid, av, wv);
    __syncthreads();
    g_ldg(A, W, K, bm, bn, 32, tid, av, wv);

    for (int kt = 0; kt < NT; kt += 2) {
        g_sts(buf1, tid, av, wv);
        if (kt + 2 < NT) g_ldg(A, W, K, bm, bn, (kt + 2) * 32, tid, av, wv);
        g_compute(buf0, wm, wn, gid, tig, acc);
        __syncthreads();
        if (kt + 2 < NT) {
            g_sts(buf0, tid, av, wv);
            if (kt + 3 < NT) g_ldg(A, W, K, bm, bn, (kt + 3) * 32, tid, av, wv);
        }
        g_compute(buf1, wm, wn, gid, tig, acc);
        __syncthreads();
    }

#pragma unroll
    for (int mt = 0; mt < 2; mt++)
#pragma unroll
        for (int nt = 0; nt < 4; nt++) {
            int row = bm + wm * 32 + mt * 16 + gid;
            int col = bn + wn * 32 + nt * 8 + tig * 2;
            float b0 = bias[col], b1 = bias[col + 1];
            float* c = acc[mt][nt];
            float* p0 = C + (size_t)row * ldc + col;
            float* p1 = C + (size_t)(row + 8) * ldc + col;
            p0[0] = c[0] + b0; p0[1] = c[1] + b1;
            p1[0] = c[2] + b0; p1[1] = c[3] + b1;
        }
}

// ---------------------------------------------------------------------------
// Persistent tensor-core LSTM, pre-split hi/lo smem.
// 128 blocks x 512 threads, 1 block/SM, all co-resident; software grid
// barrier between steps. Block tile: BM batch x 64 j x 4 gates (N=256),
// 16 warps, each warp N=16.
// smem per stage: Ah[BM*40] Al[BM*40] Bh[256*40] Bl[256*40] = 23040 floats;
// double buffer = 184320 bytes. Epilogue reuses sb as EB[BM][260].
// ---------------------------------------------------------------------------
struct PChain {
    const float* xg0;  long dxg;      // Xg(t) = xg0 + t*dxg
    float*       ho0;  long dho;      // ho(t) = ho0 + t*dho; hp(t)=ho(t-1)
    const float* hp_init;             // t==0 h (nullptr => zeros)
    const float* cp_init;             // t==0 c (nullptr => zeros)
    const float* whh;                 // [4H,H]
    float*       cbuf;                // 2 x [512,H] ping-pong
    int ldx, ldh, ldo, ldh_init;
};
struct PArgs { PChain c[2]; };

__device__ __forceinline__ float sigm(float x) { return 1.f / (1.f + expf(-x)); }

template<int BM>
__device__ __forceinline__ void l_ldg(const float* hp, int ldh, const float* whh,
                                      int H, int b0, int j0, int k0, int tid,
                                      float4* av, float4* wv) {
    if (tid < BM * 8) {
        int r = tid >> 3, fc = tid & 7;
        av[0] = *(const float4*)(hp + (size_t)(b0 + r) * ldh + k0 + fc * 4);
    }
#pragma unroll
    for (int i = 0; i < 4; i++) {
        int idx = tid + i * 512;
        int r = idx >> 3, fc = idx & 7;
        int g = r >> 6, jl = r & 63;
        wv[i] = *(const float4*)(whh + (size_t)(g * H + j0 + jl) * H + k0 + fc * 4);
    }
}

template<int BM>
__device__ __forceinline__ void l_sts(float* __restrict__ buf, int tid,
                                      const float4* av, const float4* wv) {
    float* Ah = buf;
    float* Al = buf + BM * 40;
    float* Bh = buf + 2 * BM * 40;
    float* Bl = buf + 2 * BM * 40 + 10240;
    if (tid < BM * 8) {
        int r = tid >> 3, fc = tid & 7;
        int g = fc >> 1, up = fc & 1;
        int pos = r * 40 + g * 8 + up;
        sts_split(av[0].x, Ah, Al, pos);
        sts_split(av[0].y, Ah, Al, pos + 2);
        sts_split(av[0].z, Ah, Al, pos + 4);
        sts_split(av[0].w, Ah, Al, pos + 6);
    }
#pragma unroll
    for (int i = 0; i < 4; i++) {
        int idx = tid + i * 512;
        int r = idx >> 3, fc = idx & 7;
        int g = fc >> 1, up = fc & 1;
        int pos = r * 40 + g * 8 + up;
        sts_split(wv[i].x, Bh, Bl, pos);
        sts_split(wv[i].y, Bh, Bl, pos + 2);
        sts_split(wv[i].z, Bh, Bl, pos + 4);
        sts_split(wv[i].w, Bh, Bl, pos + 6);
    }
}

template<int BM>
__device__ __forceinline__ void l_compute(const float* __restrict__ buf,
                                          int wn, int gid, int tig,
                                          float (&acc)[BM/16][2][4]) {
    constexpr int MT = BM / 16;
    const float* Ah = buf;
    const float* Al = buf + BM * 40;
    const float* Bh = buf + 2 * BM * 40;
    const float* Bl = buf + 2 * BM * 40 + 10240;
#pragma unroll
    for (int ks = 0; ks < 4; ks++) {
        unsigned ah[MT][4], al[MT][4];
#pragma unroll
        for (int mt = 0; mt < MT; mt++) {
            int o = (mt * 16 + gid) * 40 + ks * 8 + tig * 2;
            ld_frag4(Ah + o, ah[mt]);
            ld_frag4(Al + o, al[mt]);
        }
        unsigned bh[2][2], bl[2][2];
#pragma unroll
        for (int nj = 0; nj < 2; nj++) {
            int o = (wn * 16 + nj * 8 + gid) * 40 + ks * 8 + tig * 2;
            ld_frag2(Bh + o, bh[nj]);
            ld_frag2(Bl + o, bl[nj]);
        }
#pragma unroll
        for (int mt = 0; mt < MT; mt++)
#pragma unroll
            for (int nj = 0; nj < 2; nj++) {
                float* c = acc[mt][nj];
                mma8(c, ah[mt], bh[nj]);
                mma8(c, ah[mt], bl[nj]);
                mma8(c, al[mt], bh[nj]);
            }
    }
}

template<int BM>
__device__ void lstm_body(const float* Xg, const float* hp, const float* cp,
                          const float* whh, float* ho, float* co,
                          int ldx, int ldh, int ldo, int H,
                          float* sb, int j0, int b0, int tid) {
    constexpr int MT = BM / 16;
    constexpr int BUFSZ = 2 * (BM + 256) * 40;
    float* buf0 = sb;
    float* buf1 = sb + BUFSZ;
    const int lane = tid & 31;
    const int wn = tid >> 5;
    const int gid = lane >> 2, tig = lane & 3;

    if (hp) {
        float acc[MT][2][4];
#pragma unroll
        for (int mt = 0; mt < MT; mt++)
#pragma unroll
            for (int nj = 0; nj < 2; nj++)
#pragma unroll
                for (int r = 0; r < 4; r++) acc[mt][nj][r] = 0.f;

        const int NKT = H >> 5;
        float4 av[1], wv[4];

        l_ldg<BM>(hp, ldh, whh, H, b0, j0, 0, tid, av, wv);
        l_sts<BM>(buf0, tid, av, wv);
        __syncthreads();
        l_ldg<BM>(hp, ldh, whh, H, b0, j0, 32, tid, av, wv);

        for (int kt = 0; kt < NKT; kt += 2) {
            l_sts<BM>(buf1, tid, av, wv);
            if (kt + 2 < NKT) l_ldg<BM>(hp, ldh, whh, H, b0, j0, (kt + 2) * 32, tid, av, wv);
            l_compute<BM>(buf0, wn, gid, tig, acc);
            __syncthreads();
            if (kt + 2 < NKT) {
                l_sts<BM>(buf0, tid, av, wv);
                if (kt + 3 < NKT) l_ldg<BM>(hp, ldh, whh, H, b0, j0, (kt + 3) * 32, tid, av, wv);
            }
            l_compute<BM>(buf1, wn, gid, tig, acc);
            __syncthreads();
        }

        // gate exchange: EB[b_local][flat_col], stride 260
        float* EB = sb;
#pragma unroll
        for (int mt = 0; mt < MT; mt++)
#pragma unroll
            for (int nj = 0; nj < 2; nj++) {
                int col = wn * 16 + nj * 8 + tig * 2;
                float* c = acc[mt][nj];
                EB[(mt * 16 + gid) * 260 + col]         = c[0];
                EB[(mt * 16 + gid) * 260 + col + 1]     = c[1];
                EB[(mt * 16 + gid + 8) * 260 + col]     = c[2];
                EB[(mt * 16 + gid + 8) * 260 + col + 1] = c[3];
            }
        __syncthreads();
    }

    const float* EB = sb;
    const int jl = tid & 63;
    const int brow = tid >> 6;
#pragma unroll
    for (int i = 0; i < BM / 8; i++) {
        int bl_ = brow + i * 8;
        int b = b0 + bl_;
        const float* xr = Xg + (size_t)b * ldx;
        int j = j0 + jl;
        float a0 = 0.f, a1 = 0.f, a2 = 0.f, a3 = 0.f;
        if (hp) {
            a0 = EB[bl_ * 260 + jl];
            a1 = EB[bl_ * 260 + 64 + jl];
            a2 = EB[bl_ * 260 + 128 + jl];
            a3 = EB[bl_ * 260 + 192 + jl];
        }
        float gi = a0 + xr[j];
        float gf = a1 + xr[H + j];
        float gg = a2 + xr[2 * H + j];
        float go = a3 + xr[3 * H + j];
        float cpv = cp ? cp[(size_t)b * H + j] : 0.f;
        float cc = sigm(gf) * cpv + sigm(gi) * tanhf(gg);
        co[(size_t)b * H + j] = cc;
        ho[(size_t)b * ldo + j] = sigm(go) * tanhf(cc);
    }
}

template<int BM>
__global__ __launch_bounds__(512) void lstm_persist(PArgs pa, int H, int nsteps) {
    extern __shared__ float sb[];
    const PChain ch = pa.c[blockIdx.z];
    const int j0 = blockIdx.x * 64;
    const int b0 = blockIdx.y * BM;
    const int tid = threadIdx.x;
    const size_t CB = 512 * (size_t)H;

    for (int t = 0; t < nsteps; t++) {
        const float* Xg = ch.xg0 + (long)t * ch.dxg;
        const float* hp;
        const float* cp;
        int ldh;
        if (t == 0) { hp = ch.hp_init; cp = ch.cp_init; ldh = ch.ldh_init; }
        else {
            hp = ch.ho0 + (long)(t - 1) * ch.dho;
            cp = ch.cbuf + (size_t)(t & 1) * CB;
            ldh = ch.ldh;
        }
        float* ho = ch.ho0 + (long)t * ch.dho;
        float* co = ch.cbuf + (size_t)((t + 1) & 1) * CB;

        lstm_body<BM>(Xg, hp, cp, ch.whh, ho, co,
                      ch.ldx, ldh, ch.ldo, H, sb, j0, b0, tid);
        grid_barrier128();
    }
}

__global__ void build_h0c0(const float* __restrict__ CO, const float* __restrict__ TO,
                           const float* __restrict__ ccf, const float* __restrict__ ctf,
                           float* __restrict__ h0, float* __restrict__ c0) {
    int idx = blockIdx.x * blockDim.x + threadIdx.x;
    if (idx >= 512 * 512) return;
    int b = idx >> 9, j = idx & 511;
    float hv, cv;
    if (j < 256) { hv = CO[((size_t)b * 48 + 47) * 512 + j];        cv = ccf[b * 256 + j]; }
    else         { hv = TO[((size_t)b * 16 + 15) * 512 + (j - 256)]; cv = ctf[b * 256 + (j - 256)]; }
    h0[idx] = hv;
    c0[idx] = cv;
}

// ---------------------------------------------------------------------------
// Single-head attention, one block per batch element.
// ---------------------------------------------------------------------------
__global__ __launch_bounds__(256) void attn_kernel(
    const float* __restrict__ Q, const float* __restrict__ KV,
    float* __restrict__ O, int Lk)
{
    const int b = blockIdx.x;
    const int tid = threadIdx.x;
    __shared__ float Qs[48][68];
    __shared__ float Ks[48][68];
    __shared__ float s[48][48];

    const float* Qb = Q + (size_t)b * 48 * 512;
    const float* Kb = KV + (size_t)b * Lk * 1024;

    float acc[9];
#pragma unroll
    for (int i = 0; i < 9; i++) acc[i] = 0.f;

    for (int e0 = 0; e0 < 512; e0 += 64) {
        __syncthreads();
        for (int idx = tid; idx < 48 * 16; idx += 256) {
            int r = idx >> 4, cc = (idx & 15) << 2;
            *(float4*)&Qs[r][cc] = *(const float4*)(Qb + (size_t)r * 512 + e0 + cc);
        }
        for (int idx = tid; idx < Lk * 16; idx += 256) {
            int r = idx >> 4, cc = (idx & 15) << 2;
            *(float4*)&Ks[r][cc] = *(const float4*)(Kb + (size_t)r * 1024 + e0 + cc);
        }
        __syncthreads();
        int pi = 0;
        for (int idx = tid; idx < 48 * Lk; idx += 256, pi++) {
            int q = idx / Lk, k = idx - q * Lk;
            float sum = 0.f;
#pragma unroll 16
            for (int e = 0; e < 64; e++) sum += Qs[q][e] * Ks[k][e];
            acc[pi] += sum;
        }
    }
    __syncthreads();
    {
        const float scale = 0.04419417382415922f;   // 1/sqrt(512)
        int pi = 0;
        for (int idx = tid; idx < 48 * Lk; idx += 256, pi++) {
            int q = idx / Lk, k = idx - q * Lk;
            s[q][k] = acc[pi] * scale;
        }
    }
    __syncthreads();
    if (tid < 48) {
        float m = -1e30f;
        for (int k = 0; k < Lk; k++) m = fmaxf(m, s[tid][k]);
        float sum = 0.f;
        for (int k = 0; k < Lk; k++) { float e = expf(s[tid][k] - m); s[tid][k] = e; sum += e; }
        float inv = 1.f / sum;
        for (int k = 0; k < Lk; k++) s[tid][k] *= inv;
    }
    __syncthreads();

    float* Ob = O + (size_t)b * 48 * 512;
    const float* Vb = KV + (size_t)b * Lk * 1024 + 512;
    for (int e0 = 0; e0 < 512; e0 += 64) {
        for (int idx = tid; idx < Lk * 16; idx += 256) {
            int r = idx >> 4, cc = (idx & 15) << 2;
            *(float4*)&Ks[r][cc] = *(const float4*)(Vb + (size_t)r * 1024 + e0 + cc);
        }
        __syncthreads();
        for (int idx = tid; idx < 48 * 64; idx += 256) {
            int q = idx >> 6, e = idx & 63;
            float sum = 0.f;
            for (int k = 0; k < Lk; k++) sum += s[q][k] * Ks[k][e];
            Ob[(size_t)q * 512 + e0 + e] = sum;
        }
        __syncthreads();
    }
}

// ---------------------------------------------------------------------------
// Exact 1.5-entmax via warp bisection; one warp per row of 128.
// ---------------------------------------------------------------------------
__global__ __launch_bounds__(256) void entmax_kernel(
    const float* __restrict__ logits, float* __restrict__ out, int nrows)
{
    int row = blockIdx.x * 8 + (threadIdx.x >> 5);
    if (row >= nrows) return;
    int lane = threadIdx.x & 31;
    const float* x = logits + (size_t)row * 128;
    float z[4];
    float m = -1e30f;
#pragma unroll
    for (int i = 0; i < 4; i++) { z[i] = x[lane + 32 * i] * 0.5f; m = fmaxf(m, z[i]); }
#pragma unroll
    for (int o = 16; o; o >>= 1) m = fmaxf(m, __shfl_xor_sync(0xffffffffu, m, o));
#pragma unroll
    for (int i = 0; i < 4; i++) z[i] -= m;
    float lo = -1.f, hi = 0.f;
    for (int it = 0; it < 35; it++) {
        float tau = 0.5f * (lo + hi);
        float f = 0.f;
#pragma unroll
        for (int i = 0; i < 4; i++) { float d = fmaxf(z[i] - tau, 0.f); f += d * d; }
#pragma unroll
        for (int o = 16; o; o >>= 1) f += __shfl_xor_sync(0xffffffffu, f, o);
        if (f >= 1.f) lo = tau; else hi = tau;
    }
    float tau = 0.5f * (lo + hi);
    float* yo = out + (size_t)row * 128;
#pragma unroll
    for (int i = 0; i < 4; i++) { float d = fmaxf(z[i] - tau, 0.f); yo[lane + 32 * i] = d * d; }
}

// ---------------------------------------------------------------------------
extern "C" void kernel_launch(void* const* d_in, const int* in_sizes, int n_in,
                              void* d_out, int out_size) {
    const int*   li          = (const int*)  d_in[0];
    const float* char_seq    = (const float*)d_in[1];
    const float* tagset      = (const float*)d_in[2];
    const float* labels      = (const float*)d_in[3];
    const float* lang_embeds = (const float*)d_in[4];
    const float* c_w_ih_f    = (const float*)d_in[5];
    const float* c_w_hh_f    = (const float*)d_in[6];
    const float* c_b_f       = (const float*)d_in[7];
    const float* c_w_ih_b    = (const float*)d_in[8];
    const float* c_w_hh_b    = (const float*)d_in[9];
    const float* c_b_b       = (const float*)d_in[10];
    const float* t_w_ih_f    = (const float*)d_in[11];
    const float* t_w_hh_f    = (const float*)d_in[12];
    const float* t_b_f       = (const float*)d_in[13];
    const float* t_w_ih_b    = (const float*)d_in[14];
    const float* t_w_hh_b    = (const float*)d_in[15];
    const float* t_b_b       = (const float*)d_in[16];
    const float* cell_w_ih   = (const float*)d_in[17];
    const float* cell_w_hh   = (const float*)d_in[18];
    const float* cell_b      = (const float*)d_in[19];
    const float* ch_in_w     = (const float*)d_in[20];
    const float* ch_in_b     = (const float*)d_in[21];
    const float* ch_out_w    = (const float*)d_in[22];
    const float* ch_out_b    = (const float*)d_in[23];
    const float* tg_in_w     = (const float*)d_in[24];
    const float* tg_in_b     = (const float*)d_in[25];
    const float* tg_out_w    = (const float*)d_in[26];
    const float* tg_out_b    = (const float*)d_in[27];
    const float* fc_w        = (const float*)d_in[28];
    const float* fc_b        = (const float*)d_in[29];
    float* OUT = (float*)d_out;

    float* S = nullptr;
    cudaGetSymbolAddress((void**)&S, g_scratch);

    const int GSM = 163840;  // gemm_mma: 2 x 20480 floats
    const int LSM = 184320;  // lstm_persist<32>: 2 x 23040 floats
    static bool attr_set = false;
    if (!attr_set) {
        cudaFuncSetAttribute(gemm_mma, cudaFuncAttributeMaxDynamicSharedMemorySize, GSM);
        cudaFuncSetAttribute(lstm_persist<32>, cudaFuncAttributeMaxDynamicSharedMemorySize, LSM);
        attr_set = true;
    }

    // 1) input prep
    prep_kernel<<<CDIV(5767168, 256), 256>>>(li, char_seq, tagset, lang_embeds,
                                             S + O_CS, S + O_TS);
    build_decin<<<CDIV(3145728, 256), 256>>>(labels, S + O_DECIN);

    // 2) input-projection GEMMs
    gemm_mma<<<dim3(8, 192), 512, GSM>>>(S + O_CS, c_w_ih_f, c_b_f, S + O_XCF, 24576, 1024, 192, 1024);
    gemm_mma<<<dim3(8, 192), 512, GSM>>>(S + O_CS, c_w_ih_b, c_b_b, S + O_XCB, 24576, 1024, 192, 1024);
    gemm_mma<<<dim3(8,  64), 512, GSM>>>(S + O_TS, t_w_ih_f, t_b_f, S + O_XTF,  8192, 1024, 128, 1024);
    gemm_mma<<<dim3(8,  64), 512, GSM>>>(S + O_TS, t_w_ih_b, t_b_b, S + O_XTB,  8192, 1024, 128, 1024);
    gemm_mma<<<dim3(16,192), 512, GSM>>>(S + O_DECIN, cell_w_ih, cell_b, S + O_XDEC, 24576, 2048, 128, 2048);

    // 3) encoder recurrences — persistent kernels
    {
        PArgs A;  // char: fwd + bwd, 48 steps, H=256, grid (4,16,2)=128 blocks
        A.c[0] = { S + O_XCF, 1024,
                   S + O_CO, 512,
                   nullptr, nullptr, c_w_hh_f, S + O_CCF,
                   48 * 1024, 48 * 512, 48 * 512, 0 };
        A.c[1] = { S + O_XCB + 47ll * 1024, -1024,
                   S + O_CO + 47ll * 512 + 256, -512,
                   nullptr, nullptr, c_w_hh_b, S + O_CCB,
                   48 * 1024, 48 * 512, 48 * 512, 0 };
        lstm_persist<32><<<dim3(4, 16, 2), 512, LSM>>>(A, 256, 48);

        PArgs T;  // tag: fwd + bwd, 16 steps, H=256
        T.c[0] = { S + O_XTF, 1024,
                   S + O_TO, 512,
                   nullptr, nullptr, t_w_hh_f, S + O_CTF,
                   16 * 1024, 16 * 512, 16 * 512, 0 };
        T.c[1] = { S + O_XTB + 15ll * 1024, -1024,
                   S + O_TO + 15ll * 512 + 256, -512,
                   nullptr, nullptr, t_w_hh_b, S + O_CTB,
                   16 * 1024, 16 * 512, 16 * 512, 0 };
        lstm_persist<32><<<dim3(4, 16, 2), 512, LSM>>>(T, 256, 16);
    }

    // 4) initial decoder state
    build_h0c0<<<1024, 256>>>(S + O_CO, S + O_TO, S + O_CCF, S + O_CTF,
                              S + O_H0, S + O_C0);

    // 5) decoder recurrence — persistent kernel, grid (8,16,1)=128 blocks
    {
        PArgs D;
        D.c[0] = { S + O_XDEC, 2048,
                   S + O_HS, 512,
                   S + O_H0, S + O_C0, cell_w_hh, S + O_DC,
                   48 * 2048, 48 * 512, 48 * 512, 512 };
        D.c[1] = D.c[0];
        lstm_persist<32><<<dim3(8, 16, 1), 512, LSM>>>(D, 512, 48);
    }

    // 6) attention projections
    gemm_mma<<<dim3(4, 192), 512, GSM>>>(S + O_HS, ch_in_w, ch_in_b, S + O_QC, 24576, 512, 512, 512);
    gemm_mma<<<dim3(4, 192), 512, GSM>>>(S + O_HS, tg_in_w, tg_in_b, S + O_QT, 24576, 512, 512, 512);
    gemm_mma<<<dim3(8, 192), 512, GSM>>>(S + O_CO, ch_in_w + 512 * 512, ch_in_b + 512,
                                         S + O_KVC, 24576, 1024, 512, 1024);
    gemm_mma<<<dim3(8,  64), 512, GSM>>>(S + O_TO, tg_in_w + 512 * 512, tg_in_b + 512,
                                         S + O_KVT,  8192, 1024, 512, 1024);

    // 7) attention cores
    attn_kernel<<<512, 256>>>(S + O_QC, S + O_KVC, S + O_OC, 48);
    attn_kernel<<<512, 256>>>(S + O_QT, S + O_KVT, S + O_OT, 16);

    // 8) output projections straight into the concat buffer
    gemm_mma<<<dim3(4, 192), 512, GSM>>>(S + O_OC, ch_out_w, ch_out_b, S + O_CAT,       24576, 512, 512, 1024);
    gemm_mma<<<dim3(4, 192), 512, GSM>>>(S + O_OT, tg_out_w, tg_out_b, S + O_CAT + 512, 24576, 512, 512, 1024);

    // 9) final FC + entmax15
    gemm_mma<<<dim3(1, 192), 512, GSM>>>(S + O_CAT, fc_w, fc_b, S + O_LOG, 24576, 128, 1024, 128);
    entmax_kernel<<<3072, 256>>>(S + O_LOG, OUT, 24576);
}

// round 12
// speedup vs baseline: 1.7455x; 1.7455x over previous
#include <cuda_runtime.h>
#include <cuda_bf16.h>
#include <math.h>

#define CDIV(a,b) (((a)+(b)-1)/(b))

// Dimensions: B=512, SC=48, ST=16, E=512, H=256, N_CHARS=128, N_TAGS=64
constexpr size_t SZ(size_t n) { return (n + 255) & ~(size_t)255; }

constexpr size_t O_CS    = 0;                                    // [512,48,192]
constexpr size_t O_TS    = O_CS    + SZ(24576ull*192);           // [512,16,128]
constexpr size_t O_DECIN = O_TS    + SZ(8192ull*128);            // [512,48,128]
constexpr size_t O_XCF   = O_DECIN + SZ(24576ull*128);           // [512,48,1024]
constexpr size_t O_XCB   = O_XCF   + SZ(24576ull*1024);
constexpr size_t O_XTF   = O_XCB   + SZ(24576ull*1024);          // [512,16,1024]
constexpr size_t O_XTB   = O_XTF   + SZ(8192ull*1024);
constexpr size_t O_XDEC  = O_XTB   + SZ(8192ull*1024);           // [512,48,2048]
constexpr size_t O_CO    = O_XDEC  + SZ(24576ull*2048);          // [512,48,512]
constexpr size_t O_TO    = O_CO    + SZ(24576ull*512);           // [512,16,512]
constexpr size_t O_HS    = O_TO    + SZ(8192ull*512);            // [512,48,512]
constexpr size_t O_CCF   = O_HS    + SZ(24576ull*512);           // 2x[512,256]
constexpr size_t O_CCB   = O_CCF   + SZ(2ull*512*256);
constexpr size_t O_CTF   = O_CCB   + SZ(2ull*512*256);
constexpr size_t O_CTB   = O_CTF   + SZ(2ull*512*256);
constexpr size_t O_DC    = O_CTB   + SZ(2ull*512*256);           // 2x[512,512]
constexpr size_t O_H0    = O_DC    + SZ(2ull*512*512);
constexpr size_t O_C0    = O_H0    + SZ(512ull*512);
constexpr size_t O_QC    = O_C0    + SZ(512ull*512);             // [512,48,512]
constexpr size_t O_QT    = O_QC    + SZ(24576ull*512);
constexpr size_t O_KVC   = O_QT    + SZ(24576ull*512);           // [512,48,1024]
constexpr size_t O_KVT   = O_KVC   + SZ(24576ull*1024);          // [512,16,1024]
constexpr size_t O_OC    = O_KVT   + SZ(8192ull*1024);           // [512,48,512]
constexpr size_t O_OT    = O_OC    + SZ(24576ull*512);
constexpr size_t O_CAT   = O_OT    + SZ(24576ull*512);           // [24576,1024]
constexpr size_t O_LOG   = O_CAT   + SZ(24576ull*1024);          // [24576,128]
constexpr size_t O_END   = O_LOG   + SZ(24576ull*128);

__device__ float g_scratch[O_END];

// ---------------------------------------------------------------------------
// grid-wide barrier for persistent kernels (always 128 blocks)
// ---------------------------------------------------------------------------
__device__ unsigned g_cnt = 0;
__device__ unsigned g_gen = 0;

__device__ __forceinline__ void grid_barrier128() {
    __syncthreads();
    __threadfence();
    if (threadIdx.x == 0) {
        volatile unsigned* vg = &g_gen;
        unsigned my = *vg;
        if (atomicInc(&g_cnt, 127u) == 127u) {
            atomicAdd(&g_gen, 1u);
        } else {
            while (*vg == my) __nanosleep(64);
        }
    }
    __syncthreads();
}

// ---------------------------------------------------------------------------
__global__ void prep_kernel(const int* __restrict__ li,
                            const float* __restrict__ char_seq,
                            const float* __restrict__ tagset,
                            const float* __restrict__ lang_embeds,
                            float* __restrict__ cs, float* __restrict__ ts) {
    int idx = blockIdx.x * blockDim.x + threadIdx.x;
    const int n1 = 512 * 48 * 192;
    const int n2 = 512 * 16 * 128;
    if (idx < n1) {
        int b = idx / (48 * 192);
        int rem = idx - b * 48 * 192;
        int s = rem / 192, k = rem - s * 192;
        float v;
        if (k < 128) v = char_seq[(b * 48 + s) * 128 + k];
        else         v = lang_embeds[li[li[b]] * 64 + (k - 128)];
        cs[idx] = v;
    } else if (idx < n1 + n2) {
        int j = idx - n1;
        int b = j / (16 * 128);
        int rem = j - b * 16 * 128;
        int s = rem / 128, k = rem - s * 128;
        float v;
        if (k < 64) v = tagset[(b * 16 + s) * 64 + k];
        else        v = lang_embeds[li[li[b]] * 64 + (k - 64)];
        ts[j] = v;
    }
}

__global__ void build_decin(const float* __restrict__ labels, float* __restrict__ decin) {
    int idx = blockIdx.x * blockDim.x + threadIdx.x;
    if (idx >= 512 * 48 * 128) return;
    int t = (idx >> 7) % 48;
    decin[idx] = (t == 0) ? 0.f : labels[idx];
}

// ---------------------------------------------------------------------------
// bf16x3 helpers. x = hi + lo (both bf16): per-product error ~2^-18.
// D += Ah*Bh + Ah*Bl + Al*Bh with fp32 accumulate (m16n8k16).
// ---------------------------------------------------------------------------
__device__ __forceinline__ void split_bf(float x0, float x1,
                                         unsigned& hi2, unsigned& lo2) {
    unsigned h;
    asm("cvt.rn.bf16x2.f32 %0, %1, %2;" : "=r"(h) : "f"(x1), "f"(x0));
    float h0 = __uint_as_float(h << 16);
    float h1 = __uint_as_float(h & 0xffff0000u);
    float l0 = x0 - h0;
    float l1 = x1 - h1;
    unsigned l;
    asm("cvt.rn.bf16x2.f32 %0, %1, %2;" : "=r"(l) : "f"(l1), "f"(l0));
    hi2 = h; lo2 = l;
}

__device__ __forceinline__ void mma16bf(float* c, const unsigned* a, const unsigned* b) {
    asm volatile(
        "mma.sync.aligned.m16n8k16.row.col.f32.bf16.bf16.f32 "
        "{%0,%1,%2,%3}, {%4,%5,%6,%7}, {%8,%9}, {%0,%1,%2,%3};\n"
        : "+f"(c[0]), "+f"(c[1]), "+f"(c[2]), "+f"(c[3])
        : "r"(a[0]), "r"(a[1]), "r"(a[2]), "r"(a[3]), "r"(b[0]), "r"(b[1]));
}

// k2 permutation within each 8-word group so the fragment pair (k2, k2+4)
// is one LDS.64: pos = group*8 + (k2&3)*2 + ((k2>>2)&1)
__device__ __forceinline__ int permk2(int k2) {
    return (k2 >> 3) * 8 + (k2 & 3) * 2 + ((k2 >> 2) & 1);
}

// ---------------------------------------------------------------------------
// GEMM: C[m,n] = sum_k A[m,k]*W[n,k] + bias[n]. 128x128 tile, k-step 32,
// double-buffered, 512 threads = 16 warps (4m x 4n), warp tile 32x32.
// smem (uint32 words): Ah[128*24] Al Bh Bl; rows stride 24 words (16 data
// + 8 pad) -> each half-warp LDS.64 hits 32 distinct banks.
// Stage = 12288 words; double buffer = 98304 bytes.
// ---------------------------------------------------------------------------
__device__ __forceinline__ void g_ldg(const float* __restrict__ A,
                                      const float* __restrict__ W,
                                      int K, int bm, int bn, int k0, int tid,
                                      float4* av, float4* wv) {
#pragma unroll
    for (int i = 0; i < 2; i++) {
        int idx = tid + i * 512;
        int row = idx >> 3, fc = idx & 7;
        av[i] = *(const float4*)(A + (size_t)(bm + row) * K + k0 + fc * 4);
        wv[i] = *(const float4*)(W + (size_t)(bn + row) * K + k0 + fc * 4);
    }
}

__device__ __forceinline__ void g_sts(unsigned* __restrict__ buf, int tid,
                                      const float4* av, const float4* wv) {
    unsigned* Ah = buf;
    unsigned* Al = buf + 3072;
    unsigned* Bh = buf + 6144;
    unsigned* Bl = buf + 9216;
#pragma unroll
    for (int i = 0; i < 2; i++) {
        int idx = tid + i * 512;
        int row = idx >> 3, fc = idx & 7;
        int pa = row * 24 + permk2(fc * 2);
        int pb = row * 24 + permk2(fc * 2 + 1);
        unsigned h, l;
        split_bf(av[i].x, av[i].y, h, l); Ah[pa] = h; Al[pa] = l;
        split_bf(av[i].z, av[i].w, h, l); Ah[pb] = h; Al[pb] = l;
        split_bf(wv[i].x, wv[i].y, h, l); Bh[pa] = h; Bl[pa] = l;
        split_bf(wv[i].z, wv[i].w, h, l); Bh[pb] = h; Bl[pb] = l;
    }
}

__device__ __forceinline__ void g_compute(const unsigned* __restrict__ buf,
                                          int wm, int wn, int gid, int tig,
                                          float (&acc)[2][4][4]) {
    const unsigned* Ah = buf;
    const unsigned* Al = buf + 3072;
    const unsigned* Bh = buf + 6144;
    const unsigned* Bl = buf + 9216;
#pragma unroll
    for (int s = 0; s < 2; s++) {
        unsigned ah[2][4], al[2][4];
#pragma unroll
        for (int mt = 0; mt < 2; mt++) {
            int o = (wm * 32 + mt * 16 + gid) * 24 + s * 8 + tig * 2;
            uint2 p = *(const uint2*)(Ah + o);
            uint2 q = *(const uint2*)(Ah + o + 192);   // +8 rows
            ah[mt][0] = p.x; ah[mt][2] = p.y; ah[mt][1] = q.x; ah[mt][3] = q.y;
            uint2 r = *(const uint2*)(Al + o);
            uint2 t = *(const uint2*)(Al + o + 192);
            al[mt][0] = r.x; al[mt][2] = r.y; al[mt][1] = t.x; al[mt][3] = t.y;
        }
        unsigned bh[4][2], bl[4][2];
#pragma unroll
        for (int j = 0; j < 4; j++) {
            int o = (wn * 32 + j * 8 + gid) * 24 + s * 8 + tig * 2;
            uint2 p = *(const uint2*)(Bh + o);
            bh[j][0] = p.x; bh[j][1] = p.y;
            uint2 q = *(const uint2*)(Bl + o);
            bl[j][0] = q.x; bl[j][1] = q.y;
        }
#pragma unroll
        for (int mt = 0; mt < 2; mt++)
#pragma unroll
            for (int j = 0; j < 4; j++) {
                float* c = acc[mt][j];
                mma16bf(c, ah[mt], bh[j]);
                mma16bf(c, ah[mt], bl[j]);
                mma16bf(c, al[mt], bh[j]);
            }
    }
}

__global__ __launch_bounds__(512) void gemm_mma(
    const float* __restrict__ A, const float* __restrict__ W,
    const float* __restrict__ bias, float* __restrict__ C,
    int M, int N, int K, int ldc)
{
    extern __shared__ unsigned gsb[];
    unsigned* buf0 = gsb;
    unsigned* buf1 = gsb + 12288;
    const int bm = blockIdx.y * 128;
    const int bn = blockIdx.x * 128;
    const int tid = threadIdx.x;
    const int wid = tid >> 5, lane = tid & 31;
    const int wm = wid >> 2, wn = wid & 3;
    const int gid = lane >> 2, tig = lane & 3;

    float acc[2][4][4];
#pragma unroll
    for (int i = 0; i < 2; i++)
#pragma unroll
        for (int j = 0; j < 4; j++)
#pragma unroll
            for (int r = 0; r < 4; r++) acc[i][j][r] = 0.f;

    const int NT = K >> 5;
    float4 av[2], wv[2];

    g_ldg(A, W, K, bm, bn, 0, tid, av, wv);
    g_sts(buf0, tid, av, wv);
    __syncthreads();
    g_ldg(A, W, K, bm, bn, 32, tid, av, wv);

    for (int kt = 0; kt < NT; kt += 2) {
        g_sts(buf1, tid, av, wv);
        if (kt + 2 < NT) g_ldg(A, W, K, bm, bn, (kt + 2) * 32, tid, av, wv);
        g_compute(buf0, wm, wn, gid, tig, acc);
        __syncthreads();
        if (kt + 2 < NT) {
            g_sts(buf0, tid, av, wv);
            if (kt + 3 < NT) g_ldg(A, W, K, bm, bn, (kt + 3) * 32, tid, av, wv);
        }
        g_compute(buf1, wm, wn, gid, tig, acc);
        __syncthreads();
    }

#pragma unroll
    for (int mt = 0; mt < 2; mt++)
#pragma unroll
        for (int nt = 0; nt < 4; nt++) {
            int row = bm + wm * 32 + mt * 16 + gid;
            int col = bn + wn * 32 + nt * 8 + tig * 2;
            float b0 = bias[col], b1 = bias[col + 1];
            float* c = acc[mt][nt];
            float* p0 = C + (size_t)row * ldc + col;
            float* p1 = C + (size_t)(row + 8) * ldc + col;
            p0[0] = c[0] + b0; p0[1] = c[1] + b1;
            p1[0] = c[2] + b0; p1[1] = c[3] + b1;
        }
}

// ---------------------------------------------------------------------------
// Persistent tensor-core LSTM (bf16x3). 128 blocks x 512 threads, 1 block/SM,
// software grid barrier between steps. Block tile: BM batch x 64 j x 4 gates
// (N=256), 16 warps, each warp N=16.
// smem stage (words): Ah[BM*24] Al[BM*24] Bh[256*24] Bl[256*24] = 13824;
// double buffer = 110592 bytes. Epilogue reuses smem as float EB[BM][260].
// ---------------------------------------------------------------------------
struct PChain {
    const float* xg0;  long dxg;      // Xg(t) = xg0 + t*dxg
    float*       ho0;  long dho;      // ho(t) = ho0 + t*dho; hp(t)=ho(t-1)
    const float* hp_init;             // t==0 h (nullptr => zeros)
    const float* cp_init;             // t==0 c (nullptr => zeros)
    const float* whh;                 // [4H,H]
    float*       cbuf;                // 2 x [512,H] ping-pong
    int ldx, ldh, ldo, ldh_init;
};
struct PArgs { PChain c[2]; };

__device__ __forceinline__ float sigm(float x) { return 1.f / (1.f + expf(-x)); }

template<int BM>
__device__ __forceinline__ void l_ldg(const float* hp, int ldh, const float* whh,
                                      int H, int b0, int j0, int k0, int tid,
                                      float4* av, float4* wv) {
    if (tid < BM * 8) {
        int r = tid >> 3, fc = tid & 7;
        av[0] = *(const float4*)(hp + (size_t)(b0 + r) * ldh + k0 + fc * 4);
    }
#pragma unroll
    for (int i = 0; i < 4; i++) {
        int idx = tid + i * 512;
        int r = idx >> 3, fc = idx & 7;
        int g = r >> 6, jl = r & 63;
        wv[i] = *(const float4*)(whh + (size_t)(g * H + j0 + jl) * H + k0 + fc * 4);
    }
}

template<int BM>
__device__ __forceinline__ void l_sts(unsigned* __restrict__ buf, int tid,
                                      const float4* av, const float4* wv) {
    unsigned* Ah = buf;
    unsigned* Al = buf + BM * 24;
    unsigned* Bh = buf + 2 * BM * 24;
    unsigned* Bl = buf + 2 * BM * 24 + 6144;
    if (tid < BM * 8) {
        int r = tid >> 3, fc = tid & 7;
        int pa = r * 24 + permk2(fc * 2);
        int pb = r * 24 + permk2(fc * 2 + 1);
        unsigned h, l;
        split_bf(av[0].x, av[0].y, h, l); Ah[pa] = h; Al[pa] = l;
        split_bf(av[0].z, av[0].w, h, l); Ah[pb] = h; Al[pb] = l;
    }
#pragma unroll
    for (int i = 0; i < 4; i++) {
        int idx = tid + i * 512;
        int r = idx >> 3, fc = idx & 7;
        int pa = r * 24 + permk2(fc * 2);
        int pb = r * 24 + permk2(fc * 2 + 1);
        unsigned h, l;
        split_bf(wv[i].x, wv[i].y, h, l); Bh[pa] = h; Bl[pa] = l;
        split_bf(wv[i].z, wv[i].w, h, l); Bh[pb] = h; Bl[pb] = l;
    }
}

template<int BM>
__device__ __forceinline__ void l_compute(const unsigned* __restrict__ buf,
                                          int wn, int gid, int tig,
                                          float (&acc)[BM/16][2][4]) {
    constexpr int MT = BM / 16;
    const unsigned* Ah = buf;
    const unsigned* Al = buf + BM * 24;
    const unsigned* Bh = buf + 2 * BM * 24;
    const unsigned* Bl = buf + 2 * BM * 24 + 6144;
#pragma unroll
    for (int s = 0; s < 2; s++) {
        unsigned ah[MT][4], al[MT][4];
#pragma unroll
        for (int mt = 0; mt < MT; mt++) {
            int o = (mt * 16 + gid) * 24 + s * 8 + tig * 2;
            uint2 p = *(const uint2*)(Ah + o);
            uint2 q = *(const uint2*)(Ah + o + 192);
            ah[mt][0] = p.x; ah[mt][2] = p.y; ah[mt][1] = q.x; ah[mt][3] = q.y;
            uint2 r = *(const uint2*)(Al + o);
            uint2 t = *(const uint2*)(Al + o + 192);
            al[mt][0] = r.x; al[mt][2] = r.y; al[mt][1] = t.x; al[mt][3] = t.y;
        }
        unsigned bh[2][2], bl[2][2];
#pragma unroll
        for (int nj = 0; nj < 2; nj++) {
            int o = (wn * 16 + nj * 8 + gid) * 24 + s * 8 + tig * 2;
            uint2 p = *(const uint2*)(Bh + o);
            bh[nj][0] = p.x; bh[nj][1] = p.y;
            uint2 q = *(const uint2*)(Bl + o);
            bl[nj][0] = q.x; bl[nj][1] = q.y;
        }
#pragma unroll
        for (int mt = 0; mt < MT; mt++)
#pragma unroll
            for (int nj = 0; nj < 2; nj++) {
                float* c = acc[mt][nj];
                mma16bf(c, ah[mt], bh[nj]);
                mma16bf(c, ah[mt], bl[nj]);
                mma16bf(c, al[mt], bh[nj]);
            }
    }
}

template<int BM>
__device__ void lstm_body(const float* Xg, const float* hp, const float* cp,
                          const float* whh, float* ho, float* co,
                          int ldx, int ldh, int ldo, int H,
                          unsigned* sb, int j0, int b0, int tid) {
    constexpr int MT = BM / 16;
    constexpr int BUFSZ = (2 * BM + 512) * 24;   // 13824 for BM=32
    unsigned* buf0 = sb;
    unsigned* buf1 = sb + BUFSZ;
    const int lane = tid & 31;
    const int wn = tid >> 5;
    const int gid = lane >> 2, tig = lane & 3;

    if (hp) {
        float acc[MT][2][4];
#pragma unroll
        for (int mt = 0; mt < MT; mt++)
#pragma unroll
            for (int nj = 0; nj < 2; nj++)
#pragma unroll
                for (int r = 0; r < 4; r++) acc[mt][nj][r] = 0.f;

        const int NKT = H >> 5;
        float4 av[1], wv[4];

        l_ldg<BM>(hp, ldh, whh, H, b0, j0, 0, tid, av, wv);
        l_sts<BM>(buf0, tid, av, wv);
        __syncthreads();
        l_ldg<BM>(hp, ldh, whh, H, b0, j0, 32, tid, av, wv);

        for (int kt = 0; kt < NKT; kt += 2) {
            l_sts<BM>(buf1, tid, av, wv);
            if (kt + 2 < NKT) l_ldg<BM>(hp, ldh, whh, H, b0, j0, (kt + 2) * 32, tid, av, wv);
            l_compute<BM>(buf0, wn, gid, tig, acc);
            __syncthreads();
            if (kt + 2 < NKT) {
                l_sts<BM>(buf0, tid, av, wv);
                if (kt + 3 < NKT) l_ldg<BM>(hp, ldh, whh, H, b0, j0, (kt + 3) * 32, tid, av, wv);
            }
            l_compute<BM>(buf1, wn, gid, tig, acc);
            __syncthreads();
        }

        // gate exchange: EB[b_local][flat_col], stride 260 (floats)
        float* EB = (float*)sb;
#pragma unroll
        for (int mt = 0; mt < MT; mt++)
#pragma unroll
            for (int nj = 0; nj < 2; nj++) {
                int col = wn * 16 + nj * 8 + tig * 2;
                float* c = acc[mt][nj];
                EB[(mt * 16 + gid) * 260 + col]         = c[0];
                EB[(mt * 16 + gid) * 260 + col + 1]     = c[1];
                EB[(mt * 16 + gid + 8) * 260 + col]     = c[2];
                EB[(mt * 16 + gid + 8) * 260 + col + 1] = c[3];
            }
        __syncthreads();
    }

    const float* EB = (const float*)sb;
    const int jl = tid & 63;
    const int brow = tid >> 6;
#pragma unroll
    for (int i = 0; i < BM / 8; i++) {
        int bl_ = brow + i * 8;
        int b = b0 + bl_;
        const float* xr = Xg + (size_t)b * ldx;
        int j = j0 + jl;
        float a0 = 0.f, a1 = 0.f, a2 = 0.f, a3 = 0.f;
        if (hp) {
            a0 = EB[bl_ * 260 + jl];
            a1 = EB[bl_ * 260 + 64 + jl];
            a2 = EB[bl_ * 260 + 128 + jl];
            a3 = EB[bl_ * 260 + 192 + jl];
        }
        float gi = a0 + xr[j];
        float gf = a1 + xr[H + j];
        float gg = a2 + xr[2 * H + j];
        float go = a3 + xr[3 * H + j];
        float cpv = cp ? cp[(size_t)b * H + j] : 0.f;
        float cc = sigm(gf) * cpv + sigm(gi) * tanhf(gg);
        co[(size_t)b * H + j] = cc;
        ho[(size_t)b * ldo + j] = sigm(go) * tanhf(cc);
    }
}

template<int BM>
__global__ __launch_bounds__(512) void lstm_persist(PArgs pa, int H, int nsteps) {
    extern __shared__ unsigned lsb[];
    const PChain ch = pa.c[blockIdx.z];
    const int j0 = blockIdx.x * 64;
    const int b0 = blockIdx.y * BM;
    const int tid = threadIdx.x;
    const size_t CB = 512 * (size_t)H;

    for (int t = 0; t < nsteps; t++) {
        const float* Xg = ch.xg0 + (long)t * ch.dxg;
        const float* hp;
        const float* cp;
        int ldh;
        if (t == 0) { hp = ch.hp_init; cp = ch.cp_init; ldh = ch.ldh_init; }
        else {
            hp = ch.ho0 + (long)(t - 1) * ch.dho;
            cp = ch.cbuf + (size_t)(t & 1) * CB;
            ldh = ch.ldh;
        }
        float* ho = ch.ho0 + (long)t * ch.dho;
        float* co = ch.cbuf + (size_t)((t + 1) & 1) * CB;

        lstm_body<BM>(Xg, hp, cp, ch.whh, ho, co,
                      ch.ldx, ldh, ch.ldo, H, lsb, j0, b0, tid);
        grid_barrier128();
    }
}

__global__ void build_h0c0(const float* __restrict__ CO, const float* __restrict__ TO,
                           const float* __restrict__ ccf, const float* __restrict__ ctf,
                           float* __restrict__ h0, float* __restrict__ c0) {
    int idx = blockIdx.x * blockDim.x + threadIdx.x;
    if (idx >= 512 * 512) return;
    int b = idx >> 9, j = idx & 511;
    float hv, cv;
    if (j < 256) { hv = CO[((size_t)b * 48 + 47) * 512 + j];        cv = ccf[b * 256 + j]; }
    else         { hv = TO[((size_t)b * 16 + 15) * 512 + (j - 256)]; cv = ctf[b * 256 + (j - 256)]; }
    h0[idx] = hv;
    c0[idx] = cv;
}

// ---------------------------------------------------------------------------
// Single-head attention, one block per batch element.
// ---------------------------------------------------------------------------
__global__ __launch_bounds__(256) void attn_kernel(
    const float* __restrict__ Q, const float* __restrict__ KV,
    float* __restrict__ O, int Lk)
{
    const int b = blockIdx.x;
    const int tid = threadIdx.x;
    __shared__ float Qs[48][68];
    __shared__ float Ks[48][68];
    __shared__ float s[48][48];

    const float* Qb = Q + (size_t)b * 48 * 512;
    const float* Kb = KV + (size_t)b * Lk * 1024;

    float acc[9];
#pragma unroll
    for (int i = 0; i < 9; i++) acc[i] = 0.f;

    for (int e0 = 0; e0 < 512; e0 += 64) {
        __syncthreads();
        for (int idx = tid; idx < 48 * 16; idx += 256) {
            int r = idx >> 4, cc = (idx & 15) << 2;
            *(float4*)&Qs[r][cc] = *(const float4*)(Qb + (size_t)r * 512 + e0 + cc);
        }
        for (int idx = tid; idx < Lk * 16; idx += 256) {
            int r = idx >> 4, cc = (idx & 15) << 2;
            *(float4*)&Ks[r][cc] = *(const float4*)(Kb + (size_t)r * 1024 + e0 + cc);
        }
        __syncthreads();
        int pi = 0;
        for (int idx = tid; idx < 48 * Lk; idx += 256, pi++) {
            int q = idx / Lk, k = idx - q * Lk;
            float sum = 0.f;
#pragma unroll 16
            for (int e = 0; e < 64; e++) sum += Qs[q][e] * Ks[k][e];
            acc[pi] += sum;
        }
    }
    __syncthreads();
    {
        const float scale = 0.04419417382415922f;   // 1/sqrt(512)
        int pi = 0;
        for (int idx = tid; idx < 48 * Lk; idx += 256, pi++) {
            int q = idx / Lk, k = idx - q * Lk;
            s[q][k] = acc[pi] * scale;
        }
    }
    __syncthreads();
    if (tid < 48) {
        float m = -1e30f;
        for (int k = 0; k < Lk; k++) m = fmaxf(m, s[tid][k]);
        float sum = 0.f;
        for (int k = 0; k < Lk; k++) { float e = expf(s[tid][k] - m); s[tid][k] = e; sum += e; }
        float inv = 1.f / sum;
        for (int k = 0; k < Lk; k++) s[tid][k] *= inv;
    }
    __syncthreads();

    float* Ob = O + (size_t)b * 48 * 512;
    const float* Vb = KV + (size_t)b * Lk * 1024 + 512;
    for (int e0 = 0; e0 < 512; e0 += 64) {
        for (int idx = tid; idx < Lk * 16; idx += 256) {
            int r = idx >> 4, cc = (idx & 15) << 2;
            *(float4*)&Ks[r][cc] = *(const float4*)(Vb + (size_t)r * 1024 + e0 + cc);
        }
        __syncthreads();
        for (int idx = tid; idx < 48 * 64; idx += 256) {
            int q = idx >> 6, e = idx & 63;
            float sum = 0.f;
            for (int k = 0; k < Lk; k++) sum += s[q][k] * Ks[k][e];
            Ob[(size_t)q * 512 + e0 + e] = sum;
        }
        __syncthreads();
    }
}

// ---------------------------------------------------------------------------
// Exact 1.5-entmax via warp bisection; one warp per row of 128.
// ---------------------------------------------------------------------------
__global__ __launch_bounds__(256) void entmax_kernel(
    const float* __restrict__ logits, float* __restrict__ out, int nrows)
{
    int row = blockIdx.x * 8 + (threadIdx.x >> 5);
    if (row >= nrows) return;
    int lane = threadIdx.x & 31;
    const float* x = logits + (size_t)row * 128;
    float z[4];
    float m = -1e30f;
#pragma unroll
    for (int i = 0; i < 4; i++) { z[i] = x[lane + 32 * i] * 0.5f; m = fmaxf(m, z[i]); }
#pragma unroll
    for (int o = 16; o; o >>= 1) m = fmaxf(m, __shfl_xor_sync(0xffffffffu, m, o));
#pragma unroll
    for (int i = 0; i < 4; i++) z[i] -= m;
    float lo = -1.f, hi = 0.f;
    for (int it = 0; it < 35; it++) {
        float tau = 0.5f * (lo + hi);
        float f = 0.f;
#pragma unroll
        for (int i = 0; i < 4; i++) { float d = fmaxf(z[i] - tau, 0.f); f += d * d; }
#pragma unroll
        for (int o = 16; o; o >>= 1) f += __shfl_xor_sync(0xffffffffu, f, o);
        if (f >= 1.f) lo = tau; else hi = tau;
    }
    float tau = 0.5f * (lo + hi);
    float* yo = out + (size_t)row * 128;
#pragma unroll
    for (int i = 0; i < 4; i++) { float d = fmaxf(z[i] - tau, 0.f); yo[lane + 32 * i] = d * d; }
}

// ---------------------------------------------------------------------------
extern "C" void kernel_launch(void* const* d_in, const int* in_sizes, int n_in,
                              void* d_out, int out_size) {
    const int*   li          = (const int*)  d_in[0];
    const float* char_seq    = (const float*)d_in[1];
    const float* tagset      = (const float*)d_in[2];
    const float* labels      = (const float*)d_in[3];
    const float* lang_embeds = (const float*)d_in[4];
    const float* c_w_ih_f    = (const float*)d_in[5];
    const float* c_w_hh_f    = (const float*)d_in[6];
    const float* c_b_f       = (const float*)d_in[7];
    const float* c_w_ih_b    = (const float*)d_in[8];
    const float* c_w_hh_b    = (const float*)d_in[9];
    const float* c_b_b       = (const float*)d_in[10];
    const float* t_w_ih_f    = (const float*)d_in[11];
    const float* t_w_hh_f    = (const float*)d_in[12];
    const float* t_b_f       = (const float*)d_in[13];
    const float* t_w_ih_b    = (const float*)d_in[14];
    const float* t_w_hh_b    = (const float*)d_in[15];
    const float* t_b_b       = (const float*)d_in[16];
    const float* cell_w_ih   = (const float*)d_in[17];
    const float* cell_w_hh   = (const float*)d_in[18];
    const float* cell_b      = (const float*)d_in[19];
    const float* ch_in_w     = (const float*)d_in[20];
    const float* ch_in_b     = (const float*)d_in[21];
    const float* ch_out_w    = (const float*)d_in[22];
    const float* ch_out_b    = (const float*)d_in[23];
    const float* tg_in_w     = (const float*)d_in[24];
    const float* tg_in_b     = (const float*)d_in[25];
    const float* tg_out_w    = (const float*)d_in[26];
    const float* tg_out_b    = (const float*)d_in[27];
    const float* fc_w        = (const float*)d_in[28];
    const float* fc_b        = (const float*)d_in[29];
    float* OUT = (float*)d_out;

    float* S = nullptr;
    cudaGetSymbolAddress((void**)&S, g_scratch);

    const int GSM = 98304;    // gemm_mma: 2 x 12288 words
    const int LSM = 110592;   // lstm_persist<32>: 2 x 13824 words
    static bool attr_set = false;
    if (!attr_set) {
        cudaFuncSetAttribute(gemm_mma, cudaFuncAttributeMaxDynamicSharedMemorySize, GSM);
        cudaFuncSetAttribute(lstm_persist<32>, cudaFuncAttributeMaxDynamicSharedMemorySize, LSM);
        attr_set = true;
    }

    // 1) input prep
    prep_kernel<<<CDIV(5767168, 256), 256>>>(li, char_seq, tagset, lang_embeds,
                                             S + O_CS, S + O_TS);
    build_decin<<<CDIV(3145728, 256), 256>>>(labels, S + O_DECIN);

    // 2) input-projection GEMMs
    gemm_mma<<<dim3(8, 192), 512, GSM>>>(S + O_CS, c_w_ih_f, c_b_f, S + O_XCF, 24576, 1024, 192, 1024);
    gemm_mma<<<dim3(8, 192), 512, GSM>>>(S + O_CS, c_w_ih_b, c_b_b, S + O_XCB, 24576, 1024, 192, 1024);
    gemm_mma<<<dim3(8,  64), 512, GSM>>>(S + O_TS, t_w_ih_f, t_b_f, S + O_XTF,  8192, 1024, 128, 1024);
    gemm_mma<<<dim3(8,  64), 512, GSM>>>(S + O_TS, t_w_ih_b, t_b_b, S + O_XTB,  8192, 1024, 128, 1024);
    gemm_mma<<<dim3(16,192), 512, GSM>>>(S + O_DECIN, cell_w_ih, cell_b, S + O_XDEC, 24576, 2048, 128, 2048);

    // 3) encoder recurrences — persistent kernels
    {
        PArgs A;  // char: fwd + bwd, 48 steps, H=256, grid (4,16,2)=128 blocks
        A.c[0] = { S + O_XCF, 1024,
                   S + O_CO, 512,
                   nullptr, nullptr, c_w_hh_f, S + O_CCF,
                   48 * 1024, 48 * 512, 48 * 512, 0 };
        A.c[1] = { S + O_XCB + 47ll * 1024, -1024,
                   S + O_CO + 47ll * 512 + 256, -512,
                   nullptr, nullptr, c_w_hh_b, S + O_CCB,
                   48 * 1024, 48 * 512, 48 * 512, 0 };
        lstm_persist<32><<<dim3(4, 16, 2), 512, LSM>>>(A, 256, 48);

        PArgs T;  // tag: fwd + bwd, 16 steps, H=256
        T.c[0] = { S + O_XTF, 1024,
                   S + O_TO, 512,
                   nullptr, nullptr, t_w_hh_f, S + O_CTF,
                   16 * 1024, 16 * 512, 16 * 512, 0 };
        T.c[1] = { S + O_XTB + 15ll * 1024, -1024,
                   S + O_TO + 15ll * 512 + 256, -512,
                   nullptr, nullptr, t_w_hh_b, S + O_CTB,
                   16 * 1024, 16 * 512, 16 * 512, 0 };
        lstm_persist<32><<<dim3(4, 16, 2), 512, LSM>>>(T, 256, 16);
    }

    // 4) initial decoder state
    build_h0c0<<<1024, 256>>>(S + O_CO, S + O_TO, S + O_CCF, S + O_CTF,
                              S + O_H0, S + O_C0);

    // 5) decoder recurrence — persistent kernel, grid (8,16,1)=128 blocks
    {
        PArgs D;
        D.c[0] = { S + O_XDEC, 2048,
                   S + O_HS, 512,
                   S + O_H0, S + O_C0, cell_w_hh, S + O_DC,
                   48 * 2048, 48 * 512, 48 * 512, 512 };
        D.c[1] = D.c[0];
        lstm_persist<32><<<dim3(8, 16, 1), 512, LSM>>>(D, 512, 48);
    }

    // 6) attention projections
    gemm_mma<<<dim3(4, 192), 512, GSM>>>(S + O_HS, ch_in_w, ch_in_b, S + O_QC, 24576, 512, 512, 512);
    gemm_mma<<<dim3(4, 192), 512, GSM>>>(S + O_HS, tg_in_w, tg_in_b, S + O_QT, 24576, 512, 512, 512);
    gemm_mma<<<dim3(8, 192), 512, GSM>>>(S + O_CO, ch_in_w + 512 * 512, ch_in_b + 512,
                                         S + O_KVC, 24576, 1024, 512, 1024);
    gemm_mma<<<dim3(8,  64), 512, GSM>>>(S + O_TO, tg_in_w + 512 * 512, tg_in_b + 512,
                                         S + O_KVT,  8192, 1024, 512, 1024);

    // 7) attention cores
    attn_kernel<<<512, 256>>>(S + O_QC, S + O_KVC, S + O_OC, 48);
    attn_kernel<<<512, 256>>>(S + O_QT, S + O_KVT, S + O_OT, 16);

    // 8) output projections straight into the concat buffer
    gemm_mma<<<dim3(4, 192), 512, GSM>>>(S + O_OC, ch_out_w, ch_out_b, S + O_CAT,       24576, 512, 512, 1024);
    gemm_mma<<<dim3(4, 192), 512, GSM>>>(S + O_OT, tg_out_w, tg_out_b, S + O_CAT + 512, 24576, 512, 512, 1024);

    // 9) final FC + entmax15
    gemm_mma<<<dim3(1, 192), 512, GSM>>>(S + O_CAT, fc_w, fc_b, S + O_LOG, 24576, 128, 1024, 128);
    entmax_kernel<<<3072, 256>>>(S + O_LOG, OUT, 24576);
}